// round 5
// baseline (speedup 1.0000x reference)
#include <cuda_runtime.h>
#include <cuda_bf16.h>

// Problem constants
#define B_    64
#define C_    2048
#define HW_   576
#define HW4_  144          // HW_/4 float4 groups per channel row
#define NBLK  16           // k1 tiles per (t,b): 128 channels each
#define CPS   32           // channels per (block, csub)

// Scratch (allocation-free rule: __device__ globals)
__device__ float4       g_part4[2][B_][NBLK][HW4_]; // per-tile partial lum (4.7 MB)
__device__ float        g_lum_v[B_][HW_];           // lum_v row-major
__device__ float        g_lum_iT[HW_][B_];          // lum_i TRANSPOSED
__device__ double       g_sum;                      // masked mse accumulator
__device__ int          g_cnt;                      // masked pair count
__device__ unsigned int g_ticket;                   // last-block election
__device__ int          g_arrive;                   // soft grid barrier counter

// ---------------------------------------------------------------------------
// Kernel 1: streaming sum-of-squares, float4 loads (LDG.128).
// grid = (NBLK, B, 2), block = 576. q = tid%144, csub = tid/144.
// csub handles 32 contiguous channels; 4-way smem fold -> ONE float4 per q
// per tile (partials 4x smaller than R4). Also resets the reduction state
// for this replay (strictly ordered before k_fold_pair by the graph).
// ---------------------------------------------------------------------------
__global__ void __launch_bounds__(576, 3)
k_lum_partial(const float* __restrict__ fv, const float* __restrict__ fi) {
    const int blk  = blockIdx.x;
    const int b    = blockIdx.y;
    const int t    = blockIdx.z;
    const int tid  = threadIdx.x;
    const int q    = tid % HW4_;
    const int csub = tid / HW4_;

    if (blk == 0 && b == 0 && t == 0 && tid == 0) {
        g_sum = 0.0; g_cnt = 0; g_ticket = 0u; g_arrive = 0;
    }

    const float* __restrict__ f = (t == 0) ? fv : fi;
    const float4* __restrict__ base = (const float4*)
        (f + ((size_t)b * C_ + (size_t)blk * 128) * HW_)
        + (size_t)csub * CPS * HW4_ + q;

    float ax = 0.f, ay = 0.f, az = 0.f, aw = 0.f;
#pragma unroll 8
    for (int it = 0; it < CPS; ++it) {
        float4 x = base[(size_t)it * HW4_];
        ax = fmaf(x.x, x.x, ax);
        ay = fmaf(x.y, x.y, ay);
        az = fmaf(x.z, x.z, az);
        aw = fmaf(x.w, x.w, aw);
    }

    __shared__ float4 sh[4][HW4_];
    sh[csub][q] = make_float4(ax, ay, az, aw);
    __syncthreads();

    if (csub == 0) {
        float4 a = sh[0][q], c1 = sh[1][q], c2 = sh[2][q], c3 = sh[3][q];
        a.x += c1.x + c2.x + c3.x;
        a.y += c1.y + c2.y + c3.y;
        a.z += c1.z + c2.z + c3.z;
        a.w += c1.w + c2.w + c3.w;
        g_part4[t][b][blk][q] = a;
    }
}

// ---------------------------------------------------------------------------
// Kernel 2 (fused fold + pair): grid = 64, block = 64.
// Phase 1: 64 blocks cooperatively fold the 16-tile partials into
//          lum_v (row-major) / lum_iT (transposed). Coalesced reads, L2-hot.
// Soft grid barrier (g_arrive; reset by k1 -> no replay race; 64 blocks
//          are always co-resident -> no deadlock).
// Phase 2: pairwise MSE + mask + reduce + finalize (last ticket block).
// Labels are int32 (JAX x64 disabled).
// ---------------------------------------------------------------------------
__global__ void k_fold_pair(const int* __restrict__ labels,
                            float* __restrict__ out) {
    const int i = blockIdx.x;   // 0..63
    const int j = threadIdx.x;  // 0..63

    // ---- Phase 1: fold. 18432 float4 outputs, 288 per block. ----
    for (int o = i * 288 + j; o < i * 288 + 288; o += 64) {
        const int q  = o % HW4_;
        const int tb = o / HW4_;
        const int b  = tb % B_;
        const int t  = tb / B_;
        float4 s = make_float4(0.f, 0.f, 0.f, 0.f);
#pragma unroll
        for (int c = 0; c < NBLK; ++c) {
            float4 x = g_part4[t][b][c][q];
            s.x += x.x; s.y += x.y; s.z += x.z; s.w += x.w;
        }
        if (t == 0) {
            ((float4*)g_lum_v[b])[q] = s;
        } else {
            g_lum_iT[4 * q + 0][b] = s.x;
            g_lum_iT[4 * q + 1][b] = s.y;
            g_lum_iT[4 * q + 2][b] = s.z;
            g_lum_iT[4 * q + 3][b] = s.w;
        }
    }
    __threadfence();
    __syncthreads();
    if (j == 0) {
        atomicAdd(&g_arrive, 1);
        while (atomicAdd(&g_arrive, 0) < 64) { }   // spin until all folded
    }
    __syncthreads();
    __threadfence();

    // ---- Phase 2: pairwise MSE. ----
    __shared__ float  s_lv[HW_];
    __shared__ double s_red[64];

    for (int p = j; p < HW_; p += 64) s_lv[p] = g_lum_v[i][p];
    __syncthreads();

    // sv2 = sum_p lv^2
    {
        float pv = 0.0f;
        for (int p = j; p < HW_; p += 64) {
            float v = s_lv[p];
            pv = fmaf(v, v, pv);
        }
        s_red[j] = (double)pv;
    }
    __syncthreads();
    for (int s = 32; s > 0; s >>= 1) {
        if (j < s) s_red[j] += s_red[j + s];
        __syncthreads();
    }
    const double sv2 = s_red[0];
    __syncthreads();

    // cross = sum_p lv*li,  si2 = sum_p li^2 (coalesced via transpose)
    double crossd = 0.0, si2d = 0.0;
    for (int p0 = 0; p0 < HW_; p0 += 32) {
        float cf = 0.0f, sf = 0.0f;
#pragma unroll
        for (int k = 0; k < 32; ++k) {
            int   p  = p0 + k;
            float lv = s_lv[p];
            float li = g_lum_iT[p][j];
            cf = fmaf(lv, li, cf);
            sf = fmaf(li, li, sf);
        }
        crossd += (double)cf;
        si2d   += (double)sf;
    }

    const double mse = (sv2 + si2d - 2.0 * crossd) / (double)HW_;

    const bool m = (labels[i] == labels[j]) && (i != j);
    const int cnt_i = __syncthreads_count(m);   // also a barrier

    s_red[j] = m ? mse : 0.0;
    __syncthreads();
    for (int s = 32; s > 0; s >>= 1) {
        if (j < s) s_red[j] += s_red[j + s];
        __syncthreads();
    }

    if (j == 0) {
        atomicAdd(&g_sum, s_red[0]);
        atomicAdd(&g_cnt, cnt_i);
        __threadfence();
        unsigned t = atomicAdd(&g_ticket, 1u);
        if (t == gridDim.x - 1) {
            double total = atomicAdd(&g_sum, 0.0);   // atomic read
            int    cnt   = atomicAdd(&g_cnt, 0);
            out[0] = (cnt > 0) ? (float)(total / (double)cnt) : 0.0f;
        }
    }
}

extern "C" void kernel_launch(void* const* d_in, const int* in_sizes, int n_in,
                              void* d_out, int out_size) {
    const float* fv     = (const float*)d_in[0];
    const float* fi     = (const float*)d_in[1];
    const int*   labels = (const int*)d_in[2];
    float*       out    = (float*)d_out;

    k_lum_partial<<<dim3(NBLK, B_, 2), 576>>>(fv, fi);
    k_fold_pair<<<B_, 64>>>(labels, out);
}

// round 6
// speedup vs baseline: 1.2681x; 1.2681x over previous
#include <cuda_runtime.h>
#include <cuda_bf16.h>

// Problem constants
#define B_    64
#define C_    2048
#define HW_   576
#define HW4_  144                      // HW_/4 float4 groups per channel row
#define TILE_CH 64                     // channels per tile
#define NBLK  (C_ / TILE_CH)           // 32 tiles per (t,b)
#define NTILES (2 * B_ * NBLK)         // 4096 tiles
#define CPS   (TILE_CH / 4)            // 16 channels per csub per tile
#define GRID  296                      // 2 blocks/SM * 148 SMs (co-resident)

// Scratch (allocation-free rule: __device__ globals; zero-init at load,
// reset at end of every launch -> deterministic replays)
__device__ float4       g_part4[2][B_][NBLK][HW4_]; // per-tile partial lum
__device__ float        g_lum_v[B_][HW_];           // lum_v row-major
__device__ float        g_lum_iT[HW_][B_];          // lum_i TRANSPOSED
__device__ double       g_sum;
__device__ int          g_cnt;
__device__ unsigned int g_ticket;
__device__ unsigned int g_work;                     // tile work-steal counter
__device__ unsigned int g_a1, g_d1, g_a2, g_d2;     // grid barrier arrive/depart

// ---------------------------------------------------------------------------
// One persistent kernel. grid = 296, block = 576.
// Phase A: work-stealing streaming sum-of-squares (float4 loads, smem fold).
// Barrier 1 (arrive+depart). Phase B: fold partials -> lum_v / lum_iT
// (32 blocks x 576 threads, one output each). Barrier 2. Phase C: pairwise
// MSE (64 blocks, 9 p-slices x 64 j), mask, reduce, finalize, reset state.
// Labels are int32 (JAX x64 disabled).
// ---------------------------------------------------------------------------
__global__ void __launch_bounds__(576, 2)
k_fused(const float* __restrict__ fv, const float* __restrict__ fi,
        const int* __restrict__ labels, float* __restrict__ out) {
    const int bid  = blockIdx.x;
    const int tid  = threadIdx.x;
    const int q    = tid % HW4_;
    const int csub = tid / HW4_;

    __shared__ float4   sh[4][HW4_];
    __shared__ unsigned s_tile;

    // ---- Phase A: streaming, dynamic tile stealing ----
    for (;;) {
        __syncthreads();                       // sh reuse + s_tile guard
        if (tid == 0) s_tile = atomicAdd(&g_work, 1u);
        __syncthreads();
        const unsigned tile = s_tile;
        if (tile >= NTILES) break;

        const int t   = tile / (B_ * NBLK);
        const int rem = tile % (B_ * NBLK);
        const int b   = rem / NBLK;
        const int blk = rem % NBLK;

        const float* __restrict__ f = t ? fi : fv;
        const float4* __restrict__ base = (const float4*)
            (f + ((size_t)b * C_ + (size_t)blk * TILE_CH) * HW_)
            + (size_t)csub * CPS * HW4_ + q;

        float ax = 0.f, ay = 0.f, az = 0.f, aw = 0.f;
#pragma unroll
        for (int it = 0; it < CPS; ++it) {
            float4 x = base[(size_t)it * HW4_];
            ax = fmaf(x.x, x.x, ax);
            ay = fmaf(x.y, x.y, ay);
            az = fmaf(x.z, x.z, az);
            aw = fmaf(x.w, x.w, aw);
        }
        sh[csub][q] = make_float4(ax, ay, az, aw);
        __syncthreads();
        if (csub == 0) {
            float4 a = sh[0][q], c1 = sh[1][q], c2 = sh[2][q], c3 = sh[3][q];
            a.x += c1.x + c2.x + c3.x;
            a.y += c1.y + c2.y + c3.y;
            a.z += c1.z + c2.z + c3.z;
            a.w += c1.w + c2.w + c3.w;
            g_part4[t][b][blk][q] = a;
        }
    }

    // ---- Grid barrier 1 ----
    __threadfence();
    __syncthreads();
    if (tid == 0) {
        atomicAdd(&g_a1, 1u);
        while (atomicAdd(&g_a1, 0u) < GRID) __nanosleep(64);
        atomicAdd(&g_d1, 1u);                 // resetter waits on departs
    }
    __syncthreads();

    // ---- Phase B: fold partials (blocks 0..31, one output per thread) ----
    if (bid < 32) {
        const int o  = bid * 576 + tid;       // 0..18431
        const int qq = o % HW4_;
        const int tb = o / HW4_;
        const int b  = tb % B_;
        const int t  = tb / B_;
        float4 s = make_float4(0.f, 0.f, 0.f, 0.f);
#pragma unroll
        for (int c = 0; c < NBLK; ++c) {
            float4 x = g_part4[t][b][c][qq];
            s.x += x.x; s.y += x.y; s.z += x.z; s.w += x.w;
        }
        if (t == 0) {
            ((float4*)g_lum_v[b])[qq] = s;
        } else {
            g_lum_iT[4 * qq + 0][b] = s.x;
            g_lum_iT[4 * qq + 1][b] = s.y;
            g_lum_iT[4 * qq + 2][b] = s.z;
            g_lum_iT[4 * qq + 3][b] = s.w;
        }
    }

    // ---- Grid barrier 2 ----
    __threadfence();
    __syncthreads();
    if (tid == 0) {
        atomicAdd(&g_a2, 1u);
        while (atomicAdd(&g_a2, 0u) < GRID) __nanosleep(64);
        atomicAdd(&g_d2, 1u);
    }
    __syncthreads();

    if (bid >= B_) return;                    // non-pair blocks done

    // ---- Phase C: pairwise MSE. i = bid, j = tid%64, slice = tid/64 ----
    const int i  = bid;
    const int j  = tid % 64;
    const int sl = tid / 64;                  // 0..8 (9 slices x 64 p)

    __shared__ float  s_lv[HW_];
    __shared__ double s_vv[9][64], s_cf[9][64], s_sf[9][64];
    __shared__ double s_red[64];

    s_lv[tid] = g_lum_v[i][tid];
    __syncthreads();

    {
        const int p0 = sl * 64;
        float vv0=0.f, cf0=0.f, sf0=0.f, vv1=0.f, cf1=0.f, sf1=0.f;
#pragma unroll
        for (int k = 0; k < 32; ++k) {
            float lv = s_lv[p0 + k];
            float li = g_lum_iT[p0 + k][j];
            vv0 = fmaf(lv, lv, vv0);
            cf0 = fmaf(lv, li, cf0);
            sf0 = fmaf(li, li, sf0);
        }
#pragma unroll
        for (int k = 32; k < 64; ++k) {
            float lv = s_lv[p0 + k];
            float li = g_lum_iT[p0 + k][j];
            vv1 = fmaf(lv, lv, vv1);
            cf1 = fmaf(lv, li, cf1);
            sf1 = fmaf(li, li, sf1);
        }
        s_vv[sl][j] = (double)vv0 + (double)vv1;   // chunked fp32 -> double
        s_cf[sl][j] = (double)cf0 + (double)cf1;
        s_sf[sl][j] = (double)sf0 + (double)sf1;
    }
    __syncthreads();

    bool   m   = false;
    double mse = 0.0;
    if (sl == 0) {
        double vv = 0.0, cf = 0.0, sf = 0.0;
#pragma unroll
        for (int s = 0; s < 9; ++s) {
            vv += s_vv[s][j]; cf += s_cf[s][j]; sf += s_sf[s][j];
        }
        mse = (vv + sf - 2.0 * cf) / (double)HW_;
        m = (labels[i] == labels[j]) && (i != j);
    }
    const int cnt_i = __syncthreads_count(m);     // only sl==0 can be true

    if (sl == 0) s_red[j] = m ? mse : 0.0;
    __syncthreads();
    for (int s = 32; s > 0; s >>= 1) {
        if (tid < s) s_red[tid] += s_red[tid + s];
        __syncthreads();
    }

    if (tid == 0) {
        atomicAdd(&g_sum, s_red[0]);
        atomicAdd(&g_cnt, cnt_i);
        __threadfence();
        const unsigned tk = atomicAdd(&g_ticket, 1u);
        if (tk == B_ - 1) {
            const double total = atomicAdd(&g_sum, 0.0);   // atomic read
            const int    cnt   = atomicAdd(&g_cnt, 0);
            out[0] = (cnt > 0) ? (float)(total / (double)cnt) : 0.0f;
            // wait until every block is fully past both barriers, then reset
            while (atomicAdd(&g_d1, 0u) < GRID) __nanosleep(64);
            while (atomicAdd(&g_d2, 0u) < GRID) __nanosleep(64);
            g_sum = 0.0; g_cnt = 0; g_ticket = 0u; g_work = 0u;
            g_a1 = 0u; g_d1 = 0u; g_a2 = 0u; g_d2 = 0u;
            __threadfence();
        }
    }
}

extern "C" void kernel_launch(void* const* d_in, const int* in_sizes, int n_in,
                              void* d_out, int out_size) {
    const float* fv     = (const float*)d_in[0];
    const float* fi     = (const float*)d_in[1];
    const int*   labels = (const int*)d_in[2];
    float*       out    = (float*)d_out;

    k_fused<<<GRID, 576>>>(fv, fi, labels, out);
}

// round 7
// speedup vs baseline: 1.3003x; 1.0254x over previous
#include <cuda_runtime.h>
#include <cuda_bf16.h>

// Problem constants
#define B_    64
#define C_    2048
#define HW_   576
#define HW4_  144                 // HW_/4 float4 groups per channel row
#define HALF_CH 1024              // channels per block (half of C)
#define CPS   256                 // channels per csub lane (1024/4)
#define GRID  256                 // 2*B_*2 stream units; <=296 co-resident

// Scratch (allocation-free rule: __device__ globals; zero-init at load,
// reset at end of every launch -> deterministic replays)
__device__ float4       g_part4[2][B_][2][HW4_];  // per-(t,b,half) partial lum
__device__ float        g_lum_v[B_][HW_];         // lum_v row-major
__device__ float        g_lum_iT[HW_][B_];        // lum_i TRANSPOSED
__device__ double       g_sum;
__device__ int          g_cnt;
__device__ unsigned int g_ticket;
__device__ unsigned int g_a1, g_d1, g_a2, g_d2;   // grid barrier arrive/depart

// ---------------------------------------------------------------------------
// One persistent kernel. grid = 256, block = 576.
// Phase A: BARRIER-FREE streaming sum-of-squares. Block = (t, b, half):
//   2.36 MB contiguous stream, 256 float4 loads/thread in registers,
//   ONE smem fold at the end. Perfect static load balance.
// Barrier 1. Phase B: fold 2 halves -> lum_v / lum_iT (32 blocks).
// Barrier 2. Phase C: pairwise MSE (64 blocks, 9 p-slices x 64 j),
//   mask, reduce, finalize (ticket), reset state.
// Labels are int32 (JAX x64 disabled).
// ---------------------------------------------------------------------------
__global__ void __launch_bounds__(576, 2)
k_fused(const float* __restrict__ fv, const float* __restrict__ fi,
        const int* __restrict__ labels, float* __restrict__ out) {
    const int bid  = blockIdx.x;
    const int tid  = threadIdx.x;
    const int q    = tid % HW4_;
    const int csub = tid / HW4_;

    __shared__ float4 sh[4][HW4_];

    // ---- Phase A: long contiguous stream, no barriers ----
    {
        const int t    = bid >> 7;          // 0..1
        const int rem  = bid & 127;
        const int b    = rem >> 1;          // 0..63
        const int half = rem & 1;           // 0..1

        const float* __restrict__ f = t ? fi : fv;
        const float4* __restrict__ base = (const float4*)
            (f + ((size_t)b * C_ + (size_t)half * HALF_CH) * HW_)
            + (size_t)csub * CPS * HW4_ + q;

        float ax = 0.f, ay = 0.f, az = 0.f, aw = 0.f;
#pragma unroll 16
        for (int it = 0; it < CPS; ++it) {
            float4 x = base[(size_t)it * HW4_];
            ax = fmaf(x.x, x.x, ax);
            ay = fmaf(x.y, x.y, ay);
            az = fmaf(x.z, x.z, az);
            aw = fmaf(x.w, x.w, aw);
        }
        sh[csub][q] = make_float4(ax, ay, az, aw);
        __syncthreads();
        if (csub == 0) {
            float4 a = sh[0][q], c1 = sh[1][q], c2 = sh[2][q], c3 = sh[3][q];
            a.x += c1.x + c2.x + c3.x;
            a.y += c1.y + c2.y + c3.y;
            a.z += c1.z + c2.z + c3.z;
            a.w += c1.w + c2.w + c3.w;
            g_part4[t][b][half][q] = a;
        }
    }

    // ---- Grid barrier 1 ----
    __threadfence();
    __syncthreads();
    if (tid == 0) {
        atomicAdd(&g_a1, 1u);
        while (atomicAdd(&g_a1, 0u) < GRID) __nanosleep(64);
        atomicAdd(&g_d1, 1u);               // resetter waits on departs
    }
    __syncthreads();

    // ---- Phase B: fold 2 halves (blocks 0..31, one output per thread) ----
    if (bid < 32) {
        const int o  = bid * 576 + tid;     // 0..18431
        const int qq = o % HW4_;
        const int tb = o / HW4_;
        const int b  = tb % B_;
        const int t  = tb / B_;
        float4 h0 = g_part4[t][b][0][qq];
        float4 h1 = g_part4[t][b][1][qq];
        float4 s  = make_float4(h0.x + h1.x, h0.y + h1.y,
                                h0.z + h1.z, h0.w + h1.w);
        if (t == 0) {
            ((float4*)g_lum_v[b])[qq] = s;
        } else {
            g_lum_iT[4 * qq + 0][b] = s.x;
            g_lum_iT[4 * qq + 1][b] = s.y;
            g_lum_iT[4 * qq + 2][b] = s.z;
            g_lum_iT[4 * qq + 3][b] = s.w;
        }
    }

    // ---- Grid barrier 2 ----
    __threadfence();
    __syncthreads();
    if (tid == 0) {
        atomicAdd(&g_a2, 1u);
        while (atomicAdd(&g_a2, 0u) < GRID) __nanosleep(64);
        atomicAdd(&g_d2, 1u);
    }
    __syncthreads();

    if (bid >= B_) return;                  // non-pair blocks done

    // ---- Phase C: pairwise MSE. i = bid, j = tid%64, slice = tid/64 ----
    const int i  = bid;
    const int j  = tid % 64;
    const int sl = tid / 64;                // 0..8 (9 slices x 64 p)

    __shared__ float  s_lv[HW_];
    __shared__ double s_vv[9][64], s_cf[9][64], s_sf[9][64];
    __shared__ double s_red[64];

    s_lv[tid] = g_lum_v[i][tid];
    __syncthreads();

    {
        const int p0 = sl * 64;
        float vv0=0.f, cf0=0.f, sf0=0.f, vv1=0.f, cf1=0.f, sf1=0.f;
#pragma unroll
        for (int k = 0; k < 32; ++k) {
            float lv = s_lv[p0 + k];
            float li = g_lum_iT[p0 + k][j];
            vv0 = fmaf(lv, lv, vv0);
            cf0 = fmaf(lv, li, cf0);
            sf0 = fmaf(li, li, sf0);
        }
#pragma unroll
        for (int k = 32; k < 64; ++k) {
            float lv = s_lv[p0 + k];
            float li = g_lum_iT[p0 + k][j];
            vv1 = fmaf(lv, lv, vv1);
            cf1 = fmaf(lv, li, cf1);
            sf1 = fmaf(li, li, sf1);
        }
        s_vv[sl][j] = (double)vv0 + (double)vv1;  // chunked fp32 -> double
        s_cf[sl][j] = (double)cf0 + (double)cf1;
        s_sf[sl][j] = (double)sf0 + (double)sf1;
    }
    __syncthreads();

    bool   m   = false;
    double mse = 0.0;
    if (sl == 0) {
        double vv = 0.0, cf = 0.0, sf = 0.0;
#pragma unroll
        for (int s = 0; s < 9; ++s) {
            vv += s_vv[s][j]; cf += s_cf[s][j]; sf += s_sf[s][j];
        }
        mse = (vv + sf - 2.0 * cf) / (double)HW_;
        m = (labels[i] == labels[j]) && (i != j);
    }
    const int cnt_i = __syncthreads_count(m);    // only sl==0 can be true

    if (sl == 0) s_red[j] = m ? mse : 0.0;
    __syncthreads();
    for (int s = 32; s > 0; s >>= 1) {
        if (tid < s) s_red[tid] += s_red[tid + s];
        __syncthreads();
    }

    if (tid == 0) {
        atomicAdd(&g_sum, s_red[0]);
        atomicAdd(&g_cnt, cnt_i);
        __threadfence();
        const unsigned tk = atomicAdd(&g_ticket, 1u);
        if (tk == B_ - 1) {
            const double total = atomicAdd(&g_sum, 0.0);  // atomic read
            const int    cnt   = atomicAdd(&g_cnt, 0);
            out[0] = (cnt > 0) ? (float)(total / (double)cnt) : 0.0f;
            // wait until every block is fully past both barriers, then reset
            while (atomicAdd(&g_d1, 0u) < GRID) __nanosleep(64);
            while (atomicAdd(&g_d2, 0u) < GRID) __nanosleep(64);
            g_sum = 0.0; g_cnt = 0; g_ticket = 0u;
            g_a1 = 0u; g_d1 = 0u; g_a2 = 0u; g_d2 = 0u;
            __threadfence();
        }
    }
}

extern "C" void kernel_launch(void* const* d_in, const int* in_sizes, int n_in,
                              void* d_out, int out_size) {
    const float* fv     = (const float*)d_in[0];
    const float* fi     = (const float*)d_in[1];
    const int*   labels = (const int*)d_in[2];
    float*       out    = (float*)d_out;

    k_fused<<<GRID, 576>>>(fv, fi, labels, out);
}